// round 2
// baseline (speedup 1.0000x reference)
#include <cuda_runtime.h>
#include <cstdint>
#include <cstddef>

#define HID 128
#define MAXN 50000
#define MAXE 800000

// Scratch in device globals (no allocation allowed).
__device__ float g_h[(size_t)MAXN * HID];
__device__ float g_aggr[(size_t)MAXN * HID];
__device__ float g_t[(size_t)MAXN * 2 * HID];
__device__ float g_combo[18 * HID];   // emb1[a0] + emb2[a1], a0<6, a1<3

// ---------------------------------------------------------------------------
// Precompute the 18 edge-embedding combos: combo[a0*3+a1][c] = emb1[a0][c]+emb2[a1][c]
// ---------------------------------------------------------------------------
__global__ void combo_kernel(const float* __restrict__ emb1,
                             const float* __restrict__ emb2) {
    int p = blockIdx.x;          // 0..17
    int c = threadIdx.x;         // 0..127
    g_combo[p * HID + c] = emb1[(p / 3) * HID + c] + emb2[(p % 3) * HID + c];
}

// ---------------------------------------------------------------------------
// Generic fp32 GEMM: C[M,N] = act_out( act_in(A[M,K]) @ W[N,K]^T + bias )
//   BM = 64 rows/block, 256 threads = 8 warps.
//   Warp w computes rows [w*8, w*8+8); lane l computes cols l*4..l*4+3 (x NT col-halves of 128).
//   Inner loop per k: 8 broadcast LDS (A) + NT LDS128 (W) + 32*NT FFMA.
// ACT_IN: 0=none, 1=PReLU(alpha).  ACT_OUT: 0=none, 1=relu.
// ---------------------------------------------------------------------------
template<int N, int K, int NT, int ACT_IN, int ACT_OUT>
__global__ __launch_bounds__(256)
void gemm_kernel(const float* __restrict__ A, const float* __restrict__ W,
                 const float* __restrict__ bias, float* __restrict__ C,
                 int M, const float* __restrict__ pa) {
    constexpr int KC = 32;
    constexpr int NP = N + 4;                 // pad: keeps 16B alignment, kills bank conflicts
    __shared__ __align__(16) float Ws[KC * NP];
    __shared__ __align__(16) float As[64 * KC];

    const int tid  = threadIdx.x;
    const int warp = tid >> 5;
    const int lane = tid & 31;
    const int rowBase = blockIdx.x * 64;
    float alpha = 0.0f;
    if (ACT_IN == 1) alpha = *pa;

    float4 acc[NT][8];
    #pragma unroll
    for (int t = 0; t < NT; t++)
        #pragma unroll
        for (int r = 0; r < 8; r++) acc[t][r] = make_float4(0.f, 0.f, 0.f, 0.f);

    for (int kc = 0; kc < K; kc += KC) {
        // ---- stage A tile: 64 x 32 floats, vectorized float4, PReLU applied on load
        #pragma unroll
        for (int j = 0; j < 2; j++) {
            int i   = tid + j * 256;          // 512 float4s total
            int row = i >> 3;                 // 0..63
            int kv  = (i & 7) << 2;           // 0,4,...,28
            int grow = rowBase + row;
            float4 v = make_float4(0.f, 0.f, 0.f, 0.f);
            if (grow < M)
                v = *reinterpret_cast<const float4*>(A + (size_t)grow * K + kc + kv);
            if (ACT_IN == 1) {
                v.x = v.x > 0.f ? v.x : alpha * v.x;
                v.y = v.y > 0.f ? v.y : alpha * v.y;
                v.z = v.z > 0.f ? v.z : alpha * v.z;
                v.w = v.w > 0.f ? v.w : alpha * v.w;
            }
            *reinterpret_cast<float4*>(As + row * KC + kv) = v;
        }
        // ---- stage W tile transposed: Ws[kk][c] = W[c][kc+kk]  (coalesced reads)
        for (int i = tid; i < KC * N; i += 256) {
            int c  = i >> 5;
            int kk = i & 31;
            Ws[kk * NP + c] = __ldg(W + (size_t)c * K + kc + kk);
        }
        __syncthreads();

        // ---- compute
        #pragma unroll
        for (int kk = 0; kk < KC; kk++) {
            float4 wv[NT];
            #pragma unroll
            for (int t = 0; t < NT; t++)
                wv[t] = *reinterpret_cast<const float4*>(Ws + kk * NP + t * 128 + lane * 4);
            #pragma unroll
            for (int r = 0; r < 8; r++) {
                float a = As[(warp * 8 + r) * KC + kk];   // broadcast across the warp
                #pragma unroll
                for (int t = 0; t < NT; t++) {
                    acc[t][r].x = fmaf(a, wv[t].x, acc[t][r].x);
                    acc[t][r].y = fmaf(a, wv[t].y, acc[t][r].y);
                    acc[t][r].z = fmaf(a, wv[t].z, acc[t][r].z);
                    acc[t][r].w = fmaf(a, wv[t].w, acc[t][r].w);
                }
            }
        }
        __syncthreads();
    }

    // ---- epilogue: bias + activation + store
    #pragma unroll
    for (int t = 0; t < NT; t++) {
        float4 bv = make_float4(0.f, 0.f, 0.f, 0.f);
        if (bias)
            bv = *reinterpret_cast<const float4*>(bias + t * 128 + lane * 4);
        #pragma unroll
        for (int r = 0; r < 8; r++) {
            int grow = rowBase + warp * 8 + r;
            if (grow < M) {
                float4 v = acc[t][r];
                v.x += bv.x; v.y += bv.y; v.z += bv.z; v.w += bv.w;
                if (ACT_OUT == 1) {
                    v.x = fmaxf(v.x, 0.f); v.y = fmaxf(v.y, 0.f);
                    v.z = fmaxf(v.z, 0.f); v.w = fmaxf(v.w, 0.f);
                }
                *reinterpret_cast<float4*>(C + (size_t)grow * N + t * 128 + lane * 4) = v;
            }
        }
    }
}

// ---------------------------------------------------------------------------
// Zero h rows at masked node indices (idempotent under duplicates).
// ---------------------------------------------------------------------------
__global__ void mask_kernel(const int* __restrict__ mask, int nmask) {
    int i = blockIdx.x;
    if (i < nmask) {
        int node = mask[i];
        *reinterpret_cast<float4*>(g_h + (size_t)node * HID + threadIdx.x * 4) =
            make_float4(0.f, 0.f, 0.f, 0.f);
    }
}

// ---------------------------------------------------------------------------
// aggr[i] = h[i] + combo[self-loop]  (self-loop attr = [4,0] -> combo idx 4*3+0 = 12)
// One thread per float4.
// ---------------------------------------------------------------------------
__global__ void init_kernel(int n4) {
    int i = blockIdx.x * blockDim.x + threadIdx.x;
    if (i >= n4) return;
    int c4 = i & 31;                                  // float4 index within a row
    float4 h4 = *reinterpret_cast<const float4*>(g_h + (size_t)i * 4);
    float4 cb = *reinterpret_cast<const float4*>(g_combo + 12 * HID + c4 * 4);
    float4 v;
    v.x = h4.x + cb.x; v.y = h4.y + cb.y; v.z = h4.z + cb.z; v.w = h4.w + cb.w;
    *reinterpret_cast<float4*>(g_aggr + (size_t)i * 4) = v;
}

// ---------------------------------------------------------------------------
// Edge scatter: 1 warp per edge, each lane handles 4 floats.
// Gather h[src] (L2-resident), add combo table entry, vector-reduce into aggr[dst].
// ---------------------------------------------------------------------------
__global__ __launch_bounds__(256)
void edge_kernel(const int* __restrict__ ei, const int* __restrict__ ea, int E) {
    int w    = (blockIdx.x * blockDim.x + threadIdx.x) >> 5;
    int lane = threadIdx.x & 31;
    if (w >= E) return;
    int src = ei[w];
    int dst = ei[E + w];
    int a0  = ea[2 * w];
    int a1  = ea[2 * w + 1];
    float4 h4 = *reinterpret_cast<const float4*>(g_h + (size_t)src * HID + lane * 4);
    float4 cb = *reinterpret_cast<const float4*>(g_combo + (a0 * 3 + a1) * HID + lane * 4);
    float vx = h4.x + cb.x, vy = h4.y + cb.y, vz = h4.z + cb.z, vw = h4.w + cb.w;
    float* p = g_aggr + (size_t)dst * HID + lane * 4;
    asm volatile("red.global.add.v4.f32 [%0], {%1,%2,%3,%4};"
                 :: "l"(p), "f"(vx), "f"(vy), "f"(vz), "f"(vw)
                 : "memory");
}

// ---------------------------------------------------------------------------
// Launch: combo -> gemm1(h) -> mask(h) -> init(aggr) -> edges(aggr) -> gemm2(t) -> gemm3(out)
// ---------------------------------------------------------------------------
extern "C" void kernel_launch(void* const* d_in, const int* in_sizes, int n_in,
                              void* d_out, int out_size) {
    const float* x     = (const float*)d_in[0];
    const int*   ei    = (const int*)  d_in[1];
    const int*   ea    = (const int*)  d_in[2];
    const int*   mask  = (const int*)  d_in[3];
    const float* pa    = (const float*)d_in[4];
    const float* W_enc = (const float*)d_in[5];
    const float* W1    = (const float*)d_in[6];
    const float* b1    = (const float*)d_in[7];
    const float* W2    = (const float*)d_in[8];
    const float* b2    = (const float*)d_in[9];
    const float* emb1  = (const float*)d_in[10];
    const float* emb2  = (const float*)d_in[11];
    float*       out   = (float*)d_out;

    int Nn    = in_sizes[0] / HID;   // 50000
    int E     = in_sizes[2] / 2;     // 800000
    int nmask = in_sizes[3];         // 5000

    float *hP, *aggrP, *tP;
    cudaGetSymbolAddress((void**)&hP,    g_h);
    cudaGetSymbolAddress((void**)&aggrP, g_aggr);
    cudaGetSymbolAddress((void**)&tP,    g_t);

    int mb = (Nn + 63) / 64;

    combo_kernel<<<18, 128>>>(emb1, emb2);

    // GEMM1: h = PReLU(x) @ W_enc^T
    gemm_kernel<128, 128, 1, 1, 0><<<mb, 256>>>(x, W_enc, nullptr, hP, Nn, pa);

    // Zero masked rows of h
    mask_kernel<<<nmask, 32>>>(mask, nmask);

    // Self-loop init of aggr
    int n4 = Nn * (HID / 4);
    init_kernel<<<(n4 + 255) / 256, 256>>>(n4);

    // Edge scatter (vector reductions into L2-resident aggr)
    edge_kernel<<<(E + 7) / 8, 256>>>(ei, ea, E);

    // GEMM2: t = relu(aggr @ W1^T + b1)   [N=256, K=128]
    gemm_kernel<256, 128, 2, 0, 1><<<mb, 256>>>(aggrP, W1, b1, tP, Nn, nullptr);

    // GEMM3: out = t @ W2^T + b2          [N=128, K=256]
    gemm_kernel<128, 256, 1, 0, 0><<<mb, 256>>>(tP, W2, b2, out, Nn, nullptr);
}